// round 4
// baseline (speedup 1.0000x reference)
#include <cuda_runtime.h>

#define NV 8192          // variable nodes
#define RC 4096          // check nodes
#define DCD 6            // check degree
#define EE (NV*3)        // 24576 edges
#define BB 1024          // batch
#define B4 (BB/4)        // 256 float4 columns
#define NITER 10

// Scratch (static __device__ allocations per harness rules)
__device__ float d_c2v[2][(size_t)EE*BB]; // check->var messages, double-buffered, 2x ~100MB
__device__ float d_llr[(size_t)NV*BB];    // channel LLR^T, [N][B]
__device__ int   d_cedge[RC*DCD];         // scratch: edges per check
__device__ int4  d_cinfo[RC*DCD];         // per check-slot: {edge, sib1, sib2, var}
__device__ int   d_cnt[RC];               // zero-initialized; re-zeroed by k_sort each run

static __device__ __forceinline__ float fex2(float x){ float y; asm("ex2.approx.f32 %0,%1;":"=f"(y):"f"(x)); return y; }
static __device__ __forceinline__ float flg2(float x){ float y; asm("lg2.approx.f32 %0,%1;":"=f"(y):"f"(x)); return y; }

// llr_t[v][b] = 2 * received[b][v]   (tiled transpose, coalesced both sides)
__global__ void k_transpose(const float* __restrict__ rec){
    __shared__ float tile[32][33];
    int v0 = blockIdx.x*32, b0 = blockIdx.y*32;
    int tx = threadIdx.x, ty = threadIdx.y;          // 32 x 8
#pragma unroll
    for(int i=0;i<32;i+=8)
        tile[ty+i][tx] = rec[(size_t)(b0+ty+i)*NV + (v0+tx)];
    __syncthreads();
#pragma unroll
    for(int i=0;i<32;i+=8)
        d_llr[(size_t)(v0+ty+i)*BB + (b0+tx)] = 2.0f * tile[tx][ty+i];
}

__global__ void k_build(const int* __restrict__ ec){
    int e = blockIdx.x*blockDim.x + threadIdx.x;
    if(e < EE){
        int c = ec[e];
        int s = atomicAdd(&d_cnt[c], 1);
        d_cedge[c*DCD + s] = e;
    }
}

// Sort the 6 edge ids per check (deterministic regardless of atomic order),
// emit the {edge, sib1, sib2, var} table, and re-zero d_cnt for the next run.
__global__ void k_sort(){
    int c = blockIdx.x*blockDim.x + threadIdx.x;
    if(c >= RC) return;
    int v[DCD];
#pragma unroll
    for(int j=0;j<DCD;j++) v[j] = d_cedge[c*DCD+j];
#pragma unroll
    for(int i=0;i<DCD-1;i++)
#pragma unroll
        for(int j=0;j<DCD-1-i;j++)
            if(v[j] > v[j+1]){ int t=v[j]; v[j]=v[j+1]; v[j+1]=t; }
#pragma unroll
    for(int j=0;j<DCD;j++){
        int e = v[j];
        int var = e/3, k = e - 3*var;
        int4 I;
        I.x = e;
        I.y = 3*var + ((k+1)%3);
        I.z = 3*var + ((k+2)%3);
        I.w = var;
        d_cinfo[c*DCD+j] = I;
    }
    d_cnt[c] = 0;
}

// Fused iteration: one block per check, 256 threads x 4 batch lanes.
// v2c_e = llr[v] + c2v_old[sib1] + c2v_old[sib2]   (own-edge subtract cancels)
// u = e^{-|v2c|}; leave-one-out via separate (1-u)/(1+u) prefix/suffix products:
// c2v_j = sign * min( ln((B_j+A_j)/(B_j-A_j)), 2*atanh(0.999) )
template<bool FIRST>
__global__ void __launch_bounds__(256) k_iter(const float* __restrict__ src,
                                              float* __restrict__ dst){
    int c = blockIdx.x, tid = threadIdx.x;
    const float4* __restrict__ llr4 = reinterpret_cast<const float4*>(d_llr);
    const float4* __restrict__ src4 = reinterpret_cast<const float4*>(src);
    float4* __restrict__ dst4 = reinterpret_cast<float4*>(dst);

    int eidx[DCD];
    float4 X[DCD];
#pragma unroll
    for(int j=0;j<DCD;j++){
        int4 I = d_cinfo[c*DCD+j];
        eidx[j] = I.x;
        float4 t = llr4[I.w*B4 + tid];
        if(!FIRST){
            float4 a = src4[I.y*B4 + tid];
            float4 b = src4[I.z*B4 + tid];
            t.x += a.x + b.x; t.y += a.y + b.y;
            t.z += a.z + b.z; t.w += a.w + b.w;
        }
        X[j] = t;
    }

    float4 O[DCD];
#pragma unroll
    for(int l=0;l<4;l++){
        float a[DCD], b[DCD];
        unsigned sg[DCD], st = 0u;
#pragma unroll
        for(int j=0;j<DCD;j++){
            float x = (l==0)?X[j].x:(l==1)?X[j].y:(l==2)?X[j].z:X[j].w;
            unsigned s = __float_as_uint(x) & 0x80000000u;
            sg[j] = s; st ^= s;
            float u = fex2(fabsf(x) * -1.44269504f);   // e^{-|x|}
            a[j] = 1.0f - u;                            // |tanh| numerator
            b[j] = 1.0f + u;                            // denominator
        }
        float pa[DCD], pb[DCD];
        pa[0]=1.0f; pb[0]=1.0f;
#pragma unroll
        for(int j=1;j<DCD;j++){ pa[j]=pa[j-1]*a[j-1]; pb[j]=pb[j-1]*b[j-1]; }
        float sa=1.0f, sb=1.0f;
#pragma unroll
        for(int j=DCD-1;j>=0;j--){
            float A  = pa[j]*sa;
            float Bp = pb[j]*sb;
            sa *= a[j]; sb *= b[j];
            float mag = 0.69314718f * (flg2(Bp + A) - flg2(Bp - A));
            mag = fminf(mag, 7.6004025f);               // = 2*atanh(0.999f)
            float val = __uint_as_float(__float_as_uint(mag) | (st ^ sg[j]));
            if(l==0)O[j].x=val; else if(l==1)O[j].y=val; else if(l==2)O[j].z=val; else O[j].w=val;
        }
    }
#pragma unroll
    for(int j=0;j<DCD;j++) dst4[eidx[j]*B4 + tid] = O[j];
}

// Final: out[b][v] = llr + sum of the var's 3 c2v rows (transposed write) + bits
__global__ void k_final(const float* __restrict__ c2v, float* __restrict__ out, int do_bits){
    __shared__ float tile[32][33];
    int v0 = blockIdx.x*32, b0 = blockIdx.y*32;
    int tx = threadIdx.x, ty = threadIdx.y;           // 32 x 8
#pragma unroll
    for(int i=0;i<32;i+=8){
        int v = v0+ty+i, b = b0+tx;
        float f = d_llr[(size_t)v*BB+b]
                + c2v[(size_t)(3*v  )*BB+b]
                + c2v[(size_t)(3*v+1)*BB+b]
                + c2v[(size_t)(3*v+2)*BB+b];
        tile[ty+i][tx] = f;
    }
    __syncthreads();
#pragma unroll
    for(int i=0;i<32;i+=8){
        int b = b0+ty+i, v = v0+tx;
        float f = tile[tx][ty+i];
        out[(size_t)b*NV + v] = f;
        if(do_bits)
            out[(size_t)BB*NV + (size_t)b*NV + v] = (f < 0.0f) ? 1.0f : 0.0f;
    }
}

extern "C" void kernel_launch(void* const* d_in, const int* in_sizes, int n_in,
                              void* d_out, int out_size){
    const float* rec = (const float*)d_in[0];
    const int*   ec  = (const int*)d_in[2];   // edge_check (edge_var is repeat(arange(N),3))

    k_transpose<<<dim3(NV/32, BB/32), dim3(32,8)>>>(rec);
    k_build<<<EE/256, 256>>>(ec);
    k_sort<<<RC/256, 256>>>();

    // iteration i (1..10): dst = slab[(i-1)&1]  ->  iter1 writes slab0, iter10 writes slab1
    k_iter<true><<<RC, 256>>>(d_c2v[0], d_c2v[0]);     // src unused when FIRST
    for(int it=2; it<=NITER; ++it){
        const float* src = d_c2v[(it)&1];              // slab written by previous iter
        float*       dst = d_c2v[(it-1)&1];
        k_iter<false><<<RC, 256>>>(src, dst);
    }
    int do_bits = (out_size >= 2*NV*BB);
    k_final<<<dim3(NV/32, BB/32), dim3(32,8)>>>(d_c2v[1], (float*)d_out, do_bits);
}

// round 5
// speedup vs baseline: 22.5239x; 22.5239x over previous
#include <cuda_runtime.h>

#define NV 8192          // variable nodes
#define RC 4096          // check nodes
#define DCD 6            // check degree
#define STR 7            // smem slots per check (stride 7 -> conflict-free LDS)
#define EE (NV*3)        // 24576 edges
#define BB 1024          // batch
#define NITER 10
#define TPB 512

// Small global tables only (messages never touch global memory)
__device__ int            d_cedge[RC*DCD];
__device__ int            d_cnt[RC];          // zero-init; re-zeroed by k_sort each run
__device__ unsigned short d_slotT[3][NV];     // var v, local edge k -> slot id (7c+j)

static __device__ __forceinline__ float fex2(float x){ float y; asm("ex2.approx.f32 %0,%1;":"=f"(y):"f"(x)); return y; }
static __device__ __forceinline__ float flg2(float x){ float y; asm("lg2.approx.f32 %0,%1;":"=f"(y):"f"(x)); return y; }

__global__ void k_build(const int* __restrict__ ec){
    int e = blockIdx.x*blockDim.x + threadIdx.x;
    if(e < EE){
        int c = ec[e];
        int s = atomicAdd(&d_cnt[c], 1);
        d_cedge[c*DCD + s] = e;
    }
}

// Sort each check's 6 edge ids (deterministic regardless of atomic order),
// emit var->slot tables, re-zero d_cnt for the next run.
__global__ void k_sort(){
    int c = blockIdx.x*blockDim.x + threadIdx.x;
    if(c >= RC) return;
    int v[DCD];
#pragma unroll
    for(int j=0;j<DCD;j++) v[j] = d_cedge[c*DCD+j];
#pragma unroll
    for(int i=0;i<DCD-1;i++)
#pragma unroll
        for(int j=0;j<DCD-1-i;j++)
            if(v[j] > v[j+1]){ int t=v[j]; v[j]=v[j+1]; v[j+1]=t; }
#pragma unroll
    for(int j=0;j<DCD;j++){
        int e = v[j];
        int var = e/3, k = e - 3*var;
        d_slotT[k][var] = (unsigned short)(c*STR + j);
    }
    d_cnt[c] = 0;
}

// Whole decode for ONE batch column per CTA; all state in shared memory.
// smem: msg[RC*STR] fp32 | llr[NV] fp32 | slot[3][NV] u16   = 192 KB
__global__ void __launch_bounds__(TPB) k_decode(const float* __restrict__ rec,
                                                float* __restrict__ out,
                                                int do_bits){
    extern __shared__ char sm[];
    float* msg = (float*)sm;                                   // RC*STR floats
    float* llr = (float*)(sm + (size_t)RC*STR*4);              // NV floats
    unsigned short* slt = (unsigned short*)(sm + (size_t)RC*STR*4 + (size_t)NV*4); // [3][NV]

    const int b   = blockIdx.x;
    const int tid = threadIdx.x;
    const float* __restrict__ rrow = rec + (size_t)b*NV;

    // Load channel LLRs (contiguous) and the graph tables
    for(int v = tid; v < NV; v += TPB) llr[v] = 2.0f * rrow[v];
    for(int i = tid; i < 3*NV; i += TPB) slt[i] = (&d_slotT[0][0])[i];
    __syncthreads();

    // Init v2c messages: msg[slot_k(v)] = llr[v]
    for(int v = tid; v < NV; v += TPB){
        float lv = llr[v];
        msg[slt[v]]        = lv;
        msg[slt[NV + v]]   = lv;
        msg[slt[2*NV + v]] = lv;
    }
    __syncthreads();

    for(int it = 1; it <= NITER; ++it){
        // ---- check phase: msg holds v2c, becomes c2v (in place) ----
        for(int c = tid; c < RC; c += TPB){
            int base = c*STR;
            float a[DCD], bb[DCD];
            unsigned sg[DCD], st = 0u;
#pragma unroll
            for(int j=0;j<DCD;j++){
                float x = msg[base+j];
                unsigned s = __float_as_uint(x) & 0x80000000u;
                sg[j] = s; st ^= s;
                float u = fex2(fabsf(x) * -1.44269504f);   // e^{-|x|}
                a[j]  = 1.0f - u;                           // |tanh| numerator
                bb[j] = 1.0f + u;                           // denominator
            }
            float pa[DCD], pb[DCD];
            pa[0]=1.0f; pb[0]=1.0f;
#pragma unroll
            for(int j=1;j<DCD;j++){ pa[j]=pa[j-1]*a[j-1]; pb[j]=pb[j-1]*bb[j-1]; }
            float sa=1.0f, sb=1.0f;
#pragma unroll
            for(int j=DCD-1;j>=0;j--){
                float A  = pa[j]*sa;
                float Bp = pb[j]*sb;
                sa *= a[j]; sb *= bb[j];
                float mag = 0.69314718f * (flg2(Bp + A) - flg2(Bp - A));
                mag = fminf(mag, 7.6004025f);               // = 2*atanh(0.999f)
                msg[base+j] = __uint_as_float(__float_as_uint(mag) | (st ^ sg[j]));
            }
        }
        __syncthreads();

        if(it == NITER) break;

        // ---- var phase: msg holds c2v, becomes v2c (in place) ----
        for(int v = tid; v < NV; v += TPB){
            int s0 = slt[v], s1 = slt[NV+v], s2 = slt[2*NV+v];
            float c0 = msg[s0], c1 = msg[s1], c2 = msg[s2];
            float t = llr[v] + c0 + c1 + c2;
            msg[s0] = t - c0;
            msg[s1] = t - c1;
            msg[s2] = t - c2;
        }
        __syncthreads();
    }

    // Final posterior + bits (coalesced: row b contiguous)
    float* orow = out + (size_t)b*NV;
    float* brow = out + (size_t)BB*NV + (size_t)b*NV;
    for(int v = tid; v < NV; v += TPB){
        float f = llr[v] + msg[slt[v]] + msg[slt[NV+v]] + msg[slt[2*NV+v]];
        orow[v] = f;
        if(do_bits) brow[v] = (f < 0.0f) ? 1.0f : 0.0f;
    }
}

extern "C" void kernel_launch(void* const* d_in, const int* in_sizes, int n_in,
                              void* d_out, int out_size){
    const float* rec = (const float*)d_in[0];
    const int*   ec  = (const int*)d_in[2];   // edge_check (edge_var is repeat(arange(N),3))

    static const int SMEM = (RC*STR + NV)*4 + 3*NV*2;   // 196608 B
    cudaFuncSetAttribute(k_decode, cudaFuncAttributeMaxDynamicSharedMemorySize, SMEM);

    k_build<<<EE/256, 256>>>(ec);
    k_sort<<<RC/256, 256>>>();

    int do_bits = (out_size >= 2*NV*BB);
    k_decode<<<BB, TPB, SMEM>>>(rec, (float*)d_out, do_bits);
}

// round 6
// speedup vs baseline: 24.9308x; 1.1069x over previous
#include <cuda_runtime.h>

#define NV 8192          // variable nodes
#define RC 4096          // check nodes
#define DCD 6            // check degree
#define STR 7            // smem slots per check (stride 7 -> conflict-free LDS)
#define EE (NV*3)        // 24576 edges
#define BB 1024          // batch
#define NITER 10
#define TPB 1024

// Small global tables only (messages never touch global memory)
__device__ int            d_cedge[RC*DCD];
__device__ int            d_cnt[RC];          // zero-init; re-zeroed by k_sort each run
__device__ unsigned short d_slotT[NV*4];      // var v -> {slot0, slot1, slot2, pad}

static __device__ __forceinline__ float fex2(float x){ float y; asm("ex2.approx.f32 %0,%1;":"=f"(y):"f"(x)); return y; }
static __device__ __forceinline__ float flg2(float x){ float y; asm("lg2.approx.f32 %0,%1;":"=f"(y):"f"(x)); return y; }

__global__ void k_build(const int* __restrict__ ec){
    int e = blockIdx.x*blockDim.x + threadIdx.x;
    if(e < EE){
        int c = ec[e];
        int s = atomicAdd(&d_cnt[c], 1);
        d_cedge[c*DCD + s] = e;
    }
}

// Sort each check's 6 edge ids (deterministic regardless of atomic order),
// emit packed var->slot table, re-zero d_cnt for the next run.
__global__ void k_sort(){
    int c = blockIdx.x*blockDim.x + threadIdx.x;
    if(c >= RC) return;
    int v[DCD];
#pragma unroll
    for(int j=0;j<DCD;j++) v[j] = d_cedge[c*DCD+j];
#pragma unroll
    for(int i=0;i<DCD-1;i++)
#pragma unroll
        for(int j=0;j<DCD-1-i;j++)
            if(v[j] > v[j+1]){ int t=v[j]; v[j]=v[j+1]; v[j+1]=t; }
#pragma unroll
    for(int j=0;j<DCD;j++){
        int e = v[j];
        int var = e/3, k = e - 3*var;
        d_slotT[var*4 + k] = (unsigned short)(c*STR + j);
    }
    d_cnt[c] = 0;
}

// Whole decode for ONE batch column per CTA; all state in shared memory.
// smem: msg[RC*STR] f32 (112KB) | llr[NV] f32 (32KB) | slt[NV] ushort4 (64KB) = 208KB
__global__ void __launch_bounds__(TPB) k_decode(const float* __restrict__ rec,
                                                float* __restrict__ out,
                                                int do_bits){
    extern __shared__ char sm[];
    float*   msg  = (float*)sm;                                    // RC*STR
    float*   llr  = (float*)(sm + (size_t)RC*STR*4);               // NV
    ushort4* slt4 = (ushort4*)(sm + (size_t)RC*STR*4 + (size_t)NV*4);

    const int b   = blockIdx.x;
    const int tid = threadIdx.x;
    const float* __restrict__ rrow = rec + (size_t)b*NV;

    // Load channel LLRs (contiguous) and the packed slot table
    for(int v = tid; v < NV; v += TPB) llr[v] = 2.0f * rrow[v];
    {
        const uint2* g = (const uint2*)d_slotT;
        uint2* s = (uint2*)slt4;
        for(int v = tid; v < NV; v += TPB) s[v] = g[v];
    }
    __syncthreads();

    // Init v2c messages: msg[slot_k(v)] = llr[v]
    for(int v = tid; v < NV; v += TPB){
        ushort4 s = slt4[v];
        float lv = llr[v];
        msg[s.x] = lv; msg[s.y] = lv; msg[s.z] = lv;
    }
    __syncthreads();

    for(int it = 1; it <= NITER; ++it){
        // ---- check phase: msg holds v2c, becomes c2v (in place) ----
        // a_k = sign(x) * (1 - e^{-|x|}),  b_k = 1 + e^{-|x|}  (so a/b = tanh(x/2))
        // c2v_j = clamp( ln((B_j+A_j)/(B_j-A_j)), +-2*atanh(0.999) )  -- sign emerges from A_j
#pragma unroll
        for(int cc = 0; cc < RC/TPB; ++cc){
            int base = (cc*TPB + tid)*STR;
            float a[DCD], bb[DCD];
#pragma unroll
            for(int j=0;j<DCD;j++){
                float x = msg[base+j];
                float u = fex2(fabsf(x) * -1.44269504f);
                a[j]  = copysignf(1.0f - u, x);
                bb[j] = 1.0f + u;
            }
            float pa[DCD], pb[DCD];
            pa[0]=1.0f; pb[0]=1.0f;
#pragma unroll
            for(int j=1;j<DCD;j++){ pa[j]=pa[j-1]*a[j-1]; pb[j]=pb[j-1]*bb[j-1]; }
            float sa=1.0f, sb=1.0f;
#pragma unroll
            for(int j=DCD-1;j>=0;j--){
                float A  = pa[j]*sa;
                float Bp = pb[j]*sb;
                sa *= a[j]; sb *= bb[j];
                float mag = 0.69314718f * (flg2(Bp + A) - flg2(Bp - A));
                mag = fminf(fmaxf(mag, -7.6004025f), 7.6004025f);   // 2*atanh(0.999)
                msg[base+j] = mag;
            }
        }
        __syncthreads();

        if(it == NITER) break;

        // ---- var phase: msg holds c2v, becomes v2c (in place) ----
#pragma unroll
        for(int vv = 0; vv < NV/TPB; ++vv){
            int v = vv*TPB + tid;
            ushort4 s = slt4[v];
            float c0 = msg[s.x], c1 = msg[s.y], c2 = msg[s.z];
            float t = llr[v] + c0 + c1 + c2;
            msg[s.x] = t - c0;
            msg[s.y] = t - c1;
            msg[s.z] = t - c2;
        }
        __syncthreads();
    }

    // Final posterior + bits (coalesced: row b contiguous)
    float* orow = out + (size_t)b*NV;
    float* brow = out + (size_t)BB*NV + (size_t)b*NV;
    for(int v = tid; v < NV; v += TPB){
        ushort4 s = slt4[v];
        float f = llr[v] + msg[s.x] + msg[s.y] + msg[s.z];
        orow[v] = f;
        if(do_bits) brow[v] = (f < 0.0f) ? 1.0f : 0.0f;
    }
}

extern "C" void kernel_launch(void* const* d_in, const int* in_sizes, int n_in,
                              void* d_out, int out_size){
    const float* rec = (const float*)d_in[0];
    const int*   ec  = (const int*)d_in[2];   // edge_check (edge_var is repeat(arange(N),3))

    static const int SMEM = RC*STR*4 + NV*4 + NV*8;   // 212992 B
    cudaFuncSetAttribute(k_decode, cudaFuncAttributeMaxDynamicSharedMemorySize, SMEM);

    k_build<<<EE/256, 256>>>(ec);
    k_sort<<<RC/256, 256>>>();

    int do_bits = (out_size >= 2*NV*BB);
    k_decode<<<BB, TPB, SMEM>>>(rec, (float*)d_out, do_bits);
}

// round 7
// speedup vs baseline: 28.7032x; 1.1513x over previous
#include <cuda_runtime.h>

#define NV 8192          // variable nodes
#define RC 4096          // check nodes
#define DCD 6            // check degree
#define STR 7            // smem slots per check (stride 7 -> conflict-free LDS)
#define EE (NV*3)        // 24576 edges
#define BB 1024          // batch
#define NITER 10
#define TPB 512

// Small global tables only (messages never touch global memory)
__device__ int            d_cedge[RC*DCD];
__device__ int            d_cnt[RC];          // zero-init; re-zeroed by k_sort each run
__device__ unsigned short d_slotT[NV*4];      // var v -> {slot0, slot1, slot2, pad}

static __device__ __forceinline__ float fex2(float x){ float y; asm("ex2.approx.f32 %0,%1;":"=f"(y):"f"(x)); return y; }
static __device__ __forceinline__ float flg2(float x){ float y; asm("lg2.approx.f32 %0,%1;":"=f"(y):"f"(x)); return y; }

__global__ void k_build(const int* __restrict__ ec){
    int e = blockIdx.x*blockDim.x + threadIdx.x;
    if(e < EE){
        int c = ec[e];
        int s = atomicAdd(&d_cnt[c], 1);
        d_cedge[c*DCD + s] = e;
    }
}

// Sort each check's 6 edge ids (deterministic regardless of atomic order),
// emit packed var->slot table, re-zero d_cnt for the next run.
__global__ void k_sort(){
    int c = blockIdx.x*blockDim.x + threadIdx.x;
    if(c >= RC) return;
    int v[DCD];
#pragma unroll
    for(int j=0;j<DCD;j++) v[j] = d_cedge[c*DCD+j];
#pragma unroll
    for(int i=0;i<DCD-1;i++)
#pragma unroll
        for(int j=0;j<DCD-1-i;j++)
            if(v[j] > v[j+1]){ int t=v[j]; v[j]=v[j+1]; v[j+1]=t; }
#pragma unroll
    for(int j=0;j<DCD;j++){
        int e = v[j];
        int var = e/3, k = e - 3*var;
        d_slotT[var*4 + k] = (unsigned short)(c*STR + j);
    }
    d_cnt[c] = 0;
}

// Whole decode for ONE batch column per CTA.
// smem = messages only (RC*STR floats = 112KB) -> 2 CTAs per SM.
// llr (=2*rec) and the slot table are re-read from global (L2-resident, coalesced).
__global__ void __launch_bounds__(TPB, 2) k_decode(const float* __restrict__ rec,
                                                   float* __restrict__ out,
                                                   int do_bits){
    extern __shared__ float msg[];                 // RC*STR

    const int b   = blockIdx.x;
    const int tid = threadIdx.x;
    const float* __restrict__ rrow = rec + (size_t)b*NV;
    const uint2* __restrict__ slt  = (const uint2*)d_slotT;   // {s0|s1, s2|pad}

    // Init v2c messages: msg[slot_k(v)] = 2*rec[v]
#pragma unroll
    for(int vv = 0; vv < NV/TPB; ++vv){
        int v = vv*TPB + tid;
        uint2 s = slt[v];
        float lv = 2.0f * __ldg(rrow + v);
        msg[s.x & 0xFFFF] = lv;
        msg[s.x >> 16]    = lv;
        msg[s.y & 0xFFFF] = lv;
    }
    __syncthreads();

    for(int it = 1; it <= NITER; ++it){
        // ---- check phase: msg holds v2c, becomes c2v (in place) ----
        // a_k = sign(x)*(1-e^{-|x|}), b_k = 1+e^{-|x|}  (a/b = tanh(x/2))
        // c2v_j = clamp( ln((B_j+A_j)/(B_j-A_j)), +-2*atanh(0.999) )
#pragma unroll
        for(int cc = 0; cc < RC/TPB; ++cc){
            int base = (cc*TPB + tid)*STR;
            float a[DCD], bb[DCD];
#pragma unroll
            for(int j=0;j<DCD;j++){
                float x = msg[base+j];
                float u = fex2(fabsf(x) * -1.44269504f);
                a[j]  = copysignf(1.0f - u, x);
                bb[j] = 1.0f + u;
            }
            float pa[DCD], pb[DCD];
            pa[0]=1.0f; pb[0]=1.0f;
#pragma unroll
            for(int j=1;j<DCD;j++){ pa[j]=pa[j-1]*a[j-1]; pb[j]=pb[j-1]*bb[j-1]; }
            float sa=1.0f, sb=1.0f;
#pragma unroll
            for(int j=DCD-1;j>=0;j--){
                float A  = pa[j]*sa;
                float Bp = pb[j]*sb;
                sa *= a[j]; sb *= bb[j];
                float mag = 0.69314718f * (flg2(Bp + A) - flg2(Bp - A));
                msg[base+j] = fminf(fmaxf(mag, -7.6004025f), 7.6004025f);  // 2*atanh(0.999)
            }
        }
        __syncthreads();

        if(it == NITER) break;

        // ---- var phase: msg holds c2v, becomes v2c (in place) ----
#pragma unroll
        for(int vv = 0; vv < NV/TPB; ++vv){
            int v = vv*TPB + tid;
            uint2 s = slt[v];
            int s0 = s.x & 0xFFFF, s1 = s.x >> 16, s2 = s.y & 0xFFFF;
            float c0 = msg[s0], c1 = msg[s1], c2 = msg[s2];
            float t = 2.0f * __ldg(rrow + v) + c0 + c1 + c2;
            msg[s0] = t - c0;
            msg[s1] = t - c1;
            msg[s2] = t - c2;
        }
        __syncthreads();
    }

    // Final posterior + bits (coalesced: row b contiguous)
    float* orow = out + (size_t)b*NV;
    float* brow = out + (size_t)BB*NV + (size_t)b*NV;
#pragma unroll
    for(int vv = 0; vv < NV/TPB; ++vv){
        int v = vv*TPB + tid;
        uint2 s = slt[v];
        float f = 2.0f * __ldg(rrow + v)
                + msg[s.x & 0xFFFF] + msg[s.x >> 16] + msg[s.y & 0xFFFF];
        orow[v] = f;
        if(do_bits) brow[v] = (f < 0.0f) ? 1.0f : 0.0f;
    }
}

extern "C" void kernel_launch(void* const* d_in, const int* in_sizes, int n_in,
                              void* d_out, int out_size){
    const float* rec = (const float*)d_in[0];
    const int*   ec  = (const int*)d_in[2];   // edge_check (edge_var is repeat(arange(N),3))

    static const int SMEM = RC*STR*4;          // 114688 B (messages only)
    cudaFuncSetAttribute(k_decode, cudaFuncAttributeMaxDynamicSharedMemorySize, SMEM);

    k_build<<<EE/256, 256>>>(ec);
    k_sort<<<RC/256, 256>>>();

    int do_bits = (out_size >= 2*NV*BB);
    k_decode<<<BB, TPB, SMEM>>>(rec, (float*)d_out, do_bits);
}